// round 17
// baseline (speedup 1.0000x reference)
#include <cuda_runtime.h>
#include <cuda_fp16.h>

// ---------------------------------------------------------------------------
// GIN layer: out = BN( relu( ((1+eps)x + scatter_sum(x[src]->dst)) @ W1 + b1 ) @ W2 + b2 )
// N=100000, D=256, E=1600000.
// x pre-converted to fp16; CSR counting-sort + 1-warp/node fp16 gather (fp32 acc);
// FUSED HMMA MLP: per-CTA h1 staged in smem (no gmem round-trip); BN fused.
// ---------------------------------------------------------------------------

#define NNODE 100000
#define MPAD  100096          // 782 * 128
#define EMAX  1600000
#define DIM   256
#define DIM2  512
#define KA1   256             // GEMM1 K (plain fp16)
#define KA2   512             // GEMM2 K (plain fp16)

typedef unsigned int u32;

// ----------------------------- scratch (globals) ---------------------------
__device__ __align__(1024) float  g_h2 [(size_t)NNODE * DIM];
__device__ __align__(1024) __half g_x16[(size_t)NNODE * DIM];   // fp16 copy of x
__device__ __align__(1024) __half g_A1[(size_t)MPAD * KA1];     // agg, fp16
__device__ __align__(1024) __half g_B1[(size_t)DIM2 * KA1];     // W1^T fp16
__device__ __align__(1024) __half g_B2[(size_t)DIM  * KA2];     // W2^T fp16
__device__ int   g_deg[NNODE];
__device__ int   g_off[NNODE];
__device__ int   g_cursor[NNODE];
__device__ int   g_csr[EMAX];
__device__ int   g_bsum[128];
__device__ float g_colsum[DIM];
__device__ float g_colsq[DIM];
__device__ int   g_idx64;

// ----------------------------- helpers -------------------------------------
__device__ __forceinline__ u32 smem_u32(const void* p) {
    u32 a;
    asm("{ .reg .u64 t; cvta.to.shared.u64 t, %1; cvt.u32.u64 %0, t; }" : "=r"(a) : "l"(p));
    return a;
}
__device__ __forceinline__ u32 sw128(u32 o) { return o ^ ((o >> 3) & 0x70); }

__device__ __forceinline__ void cp_async16(u32 saddr, const void* g) {
    asm volatile("cp.async.cg.shared.global [%0], [%1], 16;" :: "r"(saddr), "l"(g));
}
#define CP_COMMIT()  asm volatile("cp.async.commit_group;")
#define CP_WAIT(n)   asm volatile("cp.async.wait_group %0;" :: "n"(n) : "memory")

__device__ __forceinline__ void ldsm4(u32& r0, u32& r1, u32& r2, u32& r3, u32 addr) {
    asm volatile("ldmatrix.sync.aligned.m8n8.x4.shared.b16 {%0,%1,%2,%3}, [%4];"
                 : "=r"(r0), "=r"(r1), "=r"(r2), "=r"(r3) : "r"(addr));
}
__device__ __forceinline__ void mma16816(float* c, const u32* a, u32 b0, u32 b1) {
    asm volatile(
        "mma.sync.aligned.m16n8k16.row.col.f32.f16.f16.f32 "
        "{%0,%1,%2,%3}, {%4,%5,%6,%7}, {%8,%9}, {%0,%1,%2,%3};"
        : "+f"(c[0]), "+f"(c[1]), "+f"(c[2]), "+f"(c[3])
        : "r"(a[0]), "r"(a[1]), "r"(a[2]), "r"(a[3]), "r"(b0), "r"(b1));
}

__device__ __forceinline__ void acc_u4(float2* a, uint4 v) {
    float2 f0 = __half22float2(*(__half2*)&v.x);
    float2 f1 = __half22float2(*(__half2*)&v.y);
    float2 f2 = __half22float2(*(__half2*)&v.z);
    float2 f3 = __half22float2(*(__half2*)&v.w);
    a[0].x += f0.x; a[0].y += f0.y;
    a[1].x += f1.x; a[1].y += f1.y;
    a[2].x += f2.x; a[2].y += f2.y;
    a[3].x += f3.x; a[3].y += f3.y;
}

__device__ __forceinline__ int load_idx(const void* p, long long i) {
    if (g_idx64) return (int)((const long long*)p)[i];
    return ((const int*)p)[i];
}

// ---------------------------------------------------------------------------
// Kernel 1: zero deg/colsum/colsq + index-dtype detection
// ---------------------------------------------------------------------------
__global__ void zero_detect_kernel(const int* __restrict__ srcw, int n) {
    int t = blockIdx.x * blockDim.x + threadIdx.x;
    if (t < n) g_deg[t] = 0;
    if (t < DIM) { g_colsum[t] = 0.f; g_colsq[t] = 0.f; }
    if (t == 0) {
        int z = 1;
        for (int i = 1; i < 129; i += 2) if (srcw[i] != 0) { z = 0; break; }
        g_idx64 = z;
    }
}

// ---------------------------------------------------------------------------
// Kernel 2 (partitioned grid): conv_x || hist || conv_W1 || conv_W2
// ---------------------------------------------------------------------------
#define NB_CX 12500                  // (N*DIM/8) / 256
#define NB_H  1563                   // ceil(E / 1024)
#define NB_W1 512
#define NB_W2 512

__global__ void prep_kernel(const float* __restrict__ x,
                            const void* __restrict__ dst,
                            const float* __restrict__ W1,
                            const float* __restrict__ W2,
                            long long n8, long long ne) {
    const int b = blockIdx.x;
    if (b < NB_CX) {
        long long t = (long long)b * 256 + threadIdx.x;
        if (t >= n8) return;
        float4 a = ((const float4*)x)[2 * t];
        float4 c = ((const float4*)x)[2 * t + 1];
        uint4 o; __half2 h;
        h = __floats2half2_rn(a.x, a.y); o.x = *(u32*)&h;
        h = __floats2half2_rn(a.z, a.w); o.y = *(u32*)&h;
        h = __floats2half2_rn(c.x, c.y); o.z = *(u32*)&h;
        h = __floats2half2_rn(c.z, c.w); o.w = *(u32*)&h;
        ((uint4*)g_x16)[t] = o;
    } else if (b < NB_CX + NB_H) {
        long long base = ((long long)(b - NB_CX) * 256 + threadIdx.x) * 4;
#pragma unroll
        for (int i = 0; i < 4; i++) {
            long long e = base + i;
            if (e < ne) atomicAdd(&g_deg[load_idx(dst, e)], 1);
        }
    } else if (b < NB_CX + NB_H + NB_W1) {
        int t = (b - NB_CX - NB_H) * 256 + threadIdx.x;
        int k = t >> 9, n = t & 511;
        g_B1[(size_t)n * KA1 + k] = __float2half_rn(W1[t]);
    } else {
        int t = (b - NB_CX - NB_H - NB_W1) * 256 + threadIdx.x;
        int k = t >> 8, n = t & 255;
        g_B2[(size_t)n * KA2 + k] = __float2half_rn(W2[t]);
    }
}

// ---------------------------------------------------------------------------
// Kernel 3: per-1024-block exclusive scan of degrees
// ---------------------------------------------------------------------------
__global__ void scan1_kernel(int n) {
    __shared__ int sh[1024];
    int gid = blockIdx.x * 1024 + threadIdx.x;
    int v = (gid < n) ? g_deg[gid] : 0;
    sh[threadIdx.x] = v;
    __syncthreads();
#pragma unroll
    for (int off = 1; off < 1024; off <<= 1) {
        int t = (threadIdx.x >= off) ? sh[threadIdx.x - off] : 0;
        __syncthreads();
        sh[threadIdx.x] += t;
        __syncthreads();
    }
    if (gid < n) g_off[gid] = sh[threadIdx.x] - v;
    if (threadIdx.x == 1023) g_bsum[blockIdx.x] = sh[1023];
}

// ---------------------------------------------------------------------------
// Kernel 4: fused block-sum scan + offset/cursor write
// ---------------------------------------------------------------------------
__global__ void scan23_kernel(int n, int nb) {
    __shared__ int sb[128];
    if (threadIdx.x < 128) sb[threadIdx.x] = (threadIdx.x < nb) ? g_bsum[threadIdx.x] : 0;
    __syncthreads();
    if (threadIdx.x == 0) {
        int acc = 0;
        for (int i = 0; i < nb; i++) { int v = sb[i]; sb[i] = acc; acc += v; }
    }
    __syncthreads();
    int gid = blockIdx.x * 1024 + threadIdx.x;
    if (gid < n) {
        int o = g_off[gid] + sb[blockIdx.x];
        g_off[gid] = o;
        g_cursor[gid] = o;
    }
}

// ---------------------------------------------------------------------------
// Kernel 5: CSR fill
// ---------------------------------------------------------------------------
__global__ void fill_kernel(const void* __restrict__ src,
                            const void* __restrict__ dst, long long ne) {
    long long e = (long long)blockIdx.x * blockDim.x + threadIdx.x;
    if (e >= ne) return;
    int s = load_idx(src, e);
    int d = load_idx(dst, e);
    int pos = atomicAdd(&g_cursor[d], 1);
    g_csr[pos] = s;
}

// ---------------------------------------------------------------------------
// Kernel 6: gather (fp16 in, fp32 acc): one warp per node, 8 cols/lane.
// ---------------------------------------------------------------------------
__global__ void __launch_bounds__(256)
gather_kernel(const float* __restrict__ eps, int n) {
    const int node = blockIdx.x * 8 + (threadIdx.x >> 5);
    if (node >= n) return;
    const int lane = threadIdx.x & 31;
    const int start = g_off[node];
    const int deg   = g_deg[node];
    const uint4* xb = (const uint4*)g_x16;

    float2 a[4];
#pragma unroll
    for (int i = 0; i < 4; i++) a[i] = make_float2(0.f, 0.f);

    for (int base = 0; base < deg; base += 32) {
        const int cnt = min(32, deg - base);
        int sj = 0;
        if (lane < cnt) sj = g_csr[start + base + lane];
        int k = 0;
        for (; k + 1 < cnt; k += 2) {
            int s0 = __shfl_sync(0xffffffffu, sj, k);
            int s1 = __shfl_sync(0xffffffffu, sj, k + 1);
            uint4 v0 = __ldg(xb + (size_t)s0 * 32 + lane);
            uint4 v1 = __ldg(xb + (size_t)s1 * 32 + lane);
            acc_u4(a, v0);
            acc_u4(a, v1);
        }
        if (k < cnt) {
            int s0 = __shfl_sync(0xffffffffu, sj, k);
            uint4 v0 = __ldg(xb + (size_t)s0 * 32 + lane);
            acc_u4(a, v0);
        }
    }

    const float sc = 1.0f + eps[0];
    uint4 v = __ldg(xb + (size_t)node * 32 + lane);
    {
        float2 f0 = __half22float2(*(__half2*)&v.x);
        float2 f1 = __half22float2(*(__half2*)&v.y);
        float2 f2 = __half22float2(*(__half2*)&v.z);
        float2 f3 = __half22float2(*(__half2*)&v.w);
        a[0].x = fmaf(sc, f0.x, a[0].x); a[0].y = fmaf(sc, f0.y, a[0].y);
        a[1].x = fmaf(sc, f1.x, a[1].x); a[1].y = fmaf(sc, f1.y, a[1].y);
        a[2].x = fmaf(sc, f2.x, a[2].x); a[2].y = fmaf(sc, f2.y, a[2].y);
        a[3].x = fmaf(sc, f3.x, a[3].x); a[3].y = fmaf(sc, f3.y, a[3].y);
    }

    uint4 o; __half2 h;
    h = __floats2half2_rn(a[0].x, a[0].y); o.x = *(u32*)&h;
    h = __floats2half2_rn(a[1].x, a[1].y); o.y = *(u32*)&h;
    h = __floats2half2_rn(a[2].x, a[2].y); o.z = *(u32*)&h;
    h = __floats2half2_rn(a[3].x, a[3].y); o.w = *(u32*)&h;
    ((uint4*)(g_A1 + (size_t)node * KA1))[lane] = o;
}

// ---------------------------------------------------------------------------
// Kernel 7: FUSED MLP. One CTA owns 128 rows end-to-end.
//   smem: A1 panels (64KB) | h1 panels (128KB) | B staging (2x16KB) = 224KB
//   Phase 1 (tiles 0-15):  h1 = relu(A1 @ B1^T + b1) -> smem panels (fp16)
//   Phase 2 (tiles 16-31): h2 = h1 @ B2^T + b2 -> g_h2 (fp32) + BN stats
//   Single continuous cp.async double-buffered B pipeline across both phases.
// ---------------------------------------------------------------------------
#define SM_A1 0
#define SM_H1 65536
#define SM_ST 196608
#define SMEM_FUSED 229376

__device__ __forceinline__ void load_btile(u32 sbuf, const __half* B,
                                           int row0, int k0, int KB, int tid) {
#pragma unroll
    for (int l = 0; l < 4; l++) {
        int i = tid + l * 256;
        int r = i >> 3, c = i & 7;
        cp_async16(sbuf + sw128((u32)(r * 128 + c * 16)),
                   B + (size_t)(row0 + r) * KB + k0 + c * 8);
    }
}
__device__ __forceinline__ void issue_tile(int t, u32 sbuf, int tid) {
    if (t < 16) load_btile(sbuf, g_B1, ((t >> 2) & 3) * 128, (t & 3) * 64, KA1, tid);
    else {
        int tt = t - 16;
        load_btile(sbuf, g_B2, (tt >> 3) * 128, (tt & 7) * 64, KA2, tid);
    }
}

__global__ void __launch_bounds__(256)
fused_mlp_kernel(const float* __restrict__ b1, const float* __restrict__ b2, int M) {
    extern __shared__ char smem[];
    const u32 sbase = smem_u32(smem);
    const int tid  = threadIdx.x;
    const int lane = tid & 31;
    const int warp = tid >> 5;
    const int m0 = blockIdx.x * 128;
    const int wm = (warp & 3) * 32;
    const int wn = (warp >> 2) * 64;

    const u32 sA1 = sbase + SM_A1;
    const u32 sH1 = sbase + SM_H1;
    const u32 sST[2] = { sbase + SM_ST, sbase + SM_ST + 16384 };

    // A1 tile -> smem panels (once). 16 cp.async16 per thread.
#pragma unroll
    for (int l = 0; l < 16; l++) {
        int i = tid + l * 256;
        int r = i >> 5, c = i & 31;                     // c: 16B chunk within 512B row
        cp_async16(sA1 + (u32)(c >> 3) * 16384 + sw128((u32)(r * 128 + (c & 7) * 16)),
                   g_A1 + (size_t)(m0 + r) * KA1 + c * 8);
    }
    issue_tile(0, sST[0], tid);
    CP_COMMIT();

    float acc[2][8][4];
#pragma unroll
    for (int mt = 0; mt < 2; mt++)
#pragma unroll
        for (int j = 0; j < 8; j++)
#pragma unroll
            for (int q = 0; q < 4; q++) acc[mt][j][q] = 0.f;

    float cs[8][2], cq[8][2];
#pragma unroll
    for (int j = 0; j < 8; j++) { cs[j][0]=cs[j][1]=cq[j][0]=cq[j][1]=0.f; }

    const int ro = lane & 15;
    const int co = (lane >> 4) * 16;
    const int rl = wm + (lane >> 2);           // local row base
    const int cl = wn + (lane & 3) * 2;        // local col base (within 128-chunk)

    for (int t = 0; t < 32; t++) {
        if (t + 1 < 32) {
            issue_tile(t + 1, sST[(t + 1) & 1], tid);
            CP_COMMIT();
            CP_WAIT(1);
        } else {
            CP_WAIT(0);
        }
        __syncthreads();

        const u32 a_base = (t < 16) ? (sA1 + (u32)(t & 3) * 16384)
                                    : (sH1 + (u32)((t - 16) & 7) * 16384);
        const u32 b_base = sST[t & 1];
#pragma unroll
        for (int ks = 0; ks < 4; ks++) {
            u32 a[2][4], b[4][4];
#pragma unroll
            for (int mt = 0; mt < 2; mt++)
                ldsm4(a[mt][0], a[mt][1], a[mt][2], a[mt][3],
                      a_base + sw128((u32)((wm + mt * 16 + ro) * 128 + ks * 32 + co)));
#pragma unroll
            for (int ng = 0; ng < 4; ng++)
                ldsm4(b[ng][0], b[ng][1], b[ng][2], b[ng][3],
                      b_base + sw128((u32)((wn + ng * 16 + ro) * 128 + ks * 32 + co)));
#pragma unroll
            for (int mt = 0; mt < 2; mt++)
#pragma unroll
                for (int j = 0; j < 8; j++)
                    mma16816(acc[mt][j], a[mt], b[j >> 1][j & 1], b[j >> 1][(j & 1) + 2]);
        }

        if (t < 16) {
            if ((t & 3) == 3) {                       // end of phase-1 n-chunk
                const int nc = (t >> 2) & 3;
#pragma unroll
                for (int mt = 0; mt < 2; mt++)
#pragma unroll
                    for (int half = 0; half < 2; half++) {
                        const int row = rl + mt * 16 + half * 8;
#pragma unroll
                        for (int j = 0; j < 8; j++) {
                            const int gcol = nc * 128 + cl + j * 8;
                            float v0 = acc[mt][j][half * 2 + 0] + __ldg(b1 + gcol);
                            float v1 = acc[mt][j][half * 2 + 1] + __ldg(b1 + gcol + 1);
                            v0 = fmaxf(v0, 0.f); v1 = fmaxf(v1, 0.f);
                            __half2 h = __floats2half2_rn(v0, v1);
                            u32 addr = sH1 + (u32)(gcol >> 6) * 16384
                                     + sw128((u32)(row * 128 + (gcol & 63) * 2));
                            asm volatile("st.shared.b32 [%0], %1;" :: "r"(addr), "r"(*(u32*)&h));
                        }
                    }
#pragma unroll
                for (int mt = 0; mt < 2; mt++)
#pragma unroll
                    for (int j = 0; j < 8; j++)
#pragma unroll
                        for (int q = 0; q < 4; q++) acc[mt][j][q] = 0.f;
            }
        } else if (((t - 16) & 7) == 7) {             // end of phase-2 n-chunk
            const int n2 = (t - 16) >> 3;
#pragma unroll
            for (int mt = 0; mt < 2; mt++)
#pragma unroll
                for (int half = 0; half < 2; half++) {
                    const int row = m0 + rl + mt * 16 + half * 8;
                    if (row >= M) continue;
                    float* orow = g_h2 + (size_t)row * DIM + n2 * 128;
#pragma unroll
                    for (int j = 0; j < 8; j++) {
                        const int col = cl + j * 8;
                        float2 v;
                        v.x = acc[mt][j][half * 2 + 0] + __ldg(b2 + n2 * 128 + col);
                        v.y = acc[mt][j][half * 2 + 1] + __ldg(b2 + n2 * 128 + col + 1);
                        *(float2*)(orow + col) = v;
                        cs[j][0] += v.x;  cs[j][1] += v.y;
                        cq[j][0] += v.x * v.x;  cq[j][1] += v.y * v.y;
                    }
                }
            if (n2 == 0) {
                // stats for cols 0..127 flushed at the end with n2=1's; reset acc only
#pragma unroll
                for (int mt = 0; mt < 2; mt++)
#pragma unroll
                    for (int j = 0; j < 8; j++)
#pragma unroll
                        for (int q = 0; q < 4; q++) acc[mt][j][q] = 0.f;
                // flush stats for n2=0 now (column sets differ between chunks)
#pragma unroll
                for (int j = 0; j < 8; j++)
#pragma unroll
                    for (int c = 0; c < 2; c++) {
                        float s = cs[j][c], q = cq[j][c];
#pragma unroll
                        for (int o = 4; o < 32; o <<= 1) {
                            s += __shfl_xor_sync(0xffffffffu, s, o);
                            q += __shfl_xor_sync(0xffffffffu, q, o);
                        }
                        if ((lane >> 2) == 0) {
                            const int col = cl + j * 8 + c;
                            atomicAdd(&g_colsum[col], s);
                            atomicAdd(&g_colsq[col],  q);
                        }
                        cs[j][c] = 0.f; cq[j][c] = 0.f;
                    }
            } else {
#pragma unroll
                for (int j = 0; j < 8; j++)
#pragma unroll
                    for (int c = 0; c < 2; c++) {
                        float s = cs[j][c], q = cq[j][c];
#pragma unroll
                        for (int o = 4; o < 32; o <<= 1) {
                            s += __shfl_xor_sync(0xffffffffu, s, o);
                            q += __shfl_xor_sync(0xffffffffu, q, o);
                        }
                        if ((lane >> 2) == 0) {
                            const int col = 128 + cl + j * 8 + c;
                            atomicAdd(&g_colsum[col], s);
                            atomicAdd(&g_colsq[col],  q);
                        }
                    }
            }
        }
        __syncthreads();
    }
}

// ---------------------------------------------------------------------------
// Kernel 8: BN finalize (per-block) + apply
// ---------------------------------------------------------------------------
__global__ void __launch_bounds__(256)
bn_apply_kernel(const float* __restrict__ gamma,
                const float* __restrict__ beta,
                float* __restrict__ out, long long nq4, float invN) {
    __shared__ float s_scale[DIM], s_shift[DIM];
    const int tid = threadIdx.x;
    {
        float m  = g_colsum[tid] * invN;
        float is = rsqrtf(g_colsq[tid] * invN - m * m + 1e-5f);
        float sc = is * gamma[tid];
        s_scale[tid] = sc;
        s_shift[tid] = beta[tid] - m * sc;
    }
    __syncthreads();

    for (long long t = (long long)blockIdx.x * blockDim.x + tid; t < nq4;
         t += (long long)gridDim.x * blockDim.x) {
        int c4 = (int)(t & 63);
        float4 v  = ((const float4*)g_h2)[t];
        float4 sc = *(float4*)&s_scale[c4 * 4];
        float4 sh = *(float4*)&s_shift[c4 * 4];
        float4 o;
        o.x = fmaf(v.x, sc.x, sh.x);
        o.y = fmaf(v.y, sc.y, sh.y);
        o.z = fmaf(v.z, sc.z, sh.z);
        o.w = fmaf(v.w, sc.w, sh.w);
        ((float4*)out)[t] = o;
    }
}

// ---------------------------------------------------------------------------
// launch
// ---------------------------------------------------------------------------
extern "C" void kernel_launch(void* const* d_in, const int* in_sizes, int n_in,
                              void* d_out, int out_size) {
    const float* x     = (const float*)d_in[0];
    const void*  src   = d_in[1];
    const void*  dst   = d_in[2];
    const float* eps   = (const float*)d_in[3];
    const float* W1    = (const float*)d_in[4];
    const float* b1    = (const float*)d_in[5];
    const float* W2    = (const float*)d_in[6];
    const float* b2    = (const float*)d_in[7];
    const float* gamma = (const float*)d_in[8];
    const float* beta  = (const float*)d_in[9];
    float* out = (float*)d_out;

    const long long n = (long long)in_sizes[0] / DIM;   // 100000
    const long long e = (long long)in_sizes[1];         // 1600000
    const int ni = (int)n;
    const int nb1024 = (ni + 1023) / 1024;

    cudaFuncSetAttribute(fused_mlp_kernel, cudaFuncAttributeMaxDynamicSharedMemorySize, SMEM_FUSED);

    // 1) zero + index-dtype detect
    zero_detect_kernel<<<(ni + 255) / 256, 256>>>((const int*)src, ni);

    // 2) conv_x || hist || conv_W1 || conv_W2 (partitioned grid)
    long long n8 = n * DIM / 8;
    prep_kernel<<<NB_CX + NB_H + NB_W1 + NB_W2, 256>>>(x, dst, W1, W2, n8, e);

    // 3-5) CSR build
    scan1_kernel<<<nb1024, 1024>>>(ni);
    scan23_kernel<<<nb1024, 1024>>>(ni, nb1024);
    fill_kernel<<<(int)((e + 255) / 256), 256>>>(src, dst, e);

    // 6) gather + seed (fp16 in, fp32 acc, fp16 out -> g_A1)
    gather_kernel<<<(ni + 7) / 8, 256>>>(eps, ni);

    // 7) fused MLP (both GEMMs, h1 in smem) + BN stats
    fused_mlp_kernel<<<MPAD / 128, 256, SMEM_FUSED>>>(b1, b2, ni);

    // 8) BN finalize + apply
    long long nq4 = n * DIM / 4;
    bn_apply_kernel<<<1184, 256>>>(gamma, beta, out, nq4, 1.0f / (float)n);
}